// round 7
// baseline (speedup 1.0000x reference)
#include <cuda_runtime.h>

// CombinedLoraA: out[c, r] = sum_k x[xids[c*64+r], k] * A[wids[c], k, r]
//   x:[512,1,4096] f32  xids:[20480] i32  wids:[320] i32  A:[80,4096,64] f32
//   out:[320,1,64] f32
//
// R6: occupancy push. KR 32->16 (smem 36KB -> 4 CTAs/SM, ~50% occ vs 31%),
// traffic invariant (staging 57MB, LDS 335MB, A 84MB once per (w,kr)).
// No init kernel: each CTA computes adapter grouping in-CTA (uniform smem
// scans, ~0.6us, parallel). Output via coalesced scratch STG + reduce kernel
// (atomics cost ~7us in R5 -> reverted).

constexpr int KDIM   = 4096;
constexpr int RANK   = 64;
constexpr int CDIM   = 320;
constexpr int NADAPT = 80;
constexpr int NTOK   = 512;
constexpr int KR     = 16;               // k per range
constexpr int NKR    = KDIM / KR;        // 256
constexpr int ASPLIT = 7;                // grid 256*7 = 1792 CTAs
constexpr int NTHR   = 256;
constexpr int NPAIR  = CDIM * RANK;      // 20480
constexpr int KR4    = KR / 4;           // 4 float4 slots per row

constexpr int SMEM_BYTES = NTOK * KR * 4            // x slice  (32 KB)
                         + CDIM * 4                 // perm
                         + CDIM * 4                 // wid
                         + (NADAPT + 1) * 4;        // seg      -> ~35.9 KB

__device__ float g_scratch[NKR * NPAIR];            // 21 MB k-partials

// ---- main: one CTA = (k-range, adapter-slot) ----
__global__ __launch_bounds__(NTHR, 4) void lora_main(
    const float* __restrict__ x,
    const int*   __restrict__ xids,
    const int*   __restrict__ wids,
    const float* __restrict__ A)
{
    extern __shared__ float smem[];
    float4* xs4    = reinterpret_cast<float4*>(smem);           // 512 x 4 f4 slots
    int*    perm_s = reinterpret_cast<int*>(smem + NTOK * KR);  // +8192 floats
    int*    wid_s  = perm_s + CDIM;
    int*    seg_s  = wid_s + CDIM;

    const int tid   = threadIdx.x;
    const int kr0   = blockIdx.x * KR;
    const int aslot = blockIdx.y;

    // stage wids + x k-range for ALL 512 rows; slot = k4 ^ (t & 3)
    for (int i = tid; i < CDIM; i += NTHR) wid_s[i] = wids[i];
    for (int i = tid; i < NTOK * KR4; i += NTHR) {
        const int row = i >> 2, k4 = i & 3;
        const float4 v = *reinterpret_cast<const float4*>(
            x + (size_t)row * KDIM + kr0 + k4 * 4);
        xs4[row * KR4 + (k4 ^ (row & 3))] = v;
    }
    __syncthreads();

    // in-CTA adapter grouping: rank of (wid, c) -> perm; prefix counts -> seg
    for (int c = tid; c < CDIM; c += NTHR) {
        const int w = wid_s[c];
        int pos = 0;
#pragma unroll 8
        for (int c2 = 0; c2 < CDIM; ++c2) {
            const int w2 = wid_s[c2];
            pos += (w2 < w) || (w2 == w && c2 < c);
        }
        perm_s[pos] = c;
    }
    if (tid < NADAPT + 1) {
        int s = 0;
#pragma unroll 8
        for (int c2 = 0; c2 < CDIM; ++c2) s += (wid_s[c2] < tid);
        seg_s[tid] = s;
    }
    __syncthreads();

    const int r = tid & 63;          // rank index (lane-contiguous)
    const int g = tid >> 6;          // 4 independent thread-groups
    const int w_lo = (aslot * NADAPT) / ASPLIT;
    const int w_hi = ((aslot + 1) * NADAPT) / ASPLIT;

    float* __restrict__ scr = g_scratch + (size_t)blockIdx.x * NPAIR;

    for (int w = w_lo + g; w < w_hi; w += 4) {
        const int lo = seg_s[w], hi = seg_s[w + 1];
        if (lo >= hi) continue;

        // A[w, kr0..kr0+16, r] -> 16 registers (coalesced over r)
        float a[KR];
        const float* __restrict__ Ap = A + ((size_t)w * KDIM + kr0) * RANK + r;
#pragma unroll
        for (int j = 0; j < KR; ++j) a[j] = Ap[j * RANK];

        // software-pipelined token fetch
        int ci = lo;
        int c  = perm_s[ci];
        int t  = xids[c * 64 + r];
        while (ci < hi) {
            const int c_cur = c, t_cur = t;
            ++ci;
            if (ci < hi) { c = perm_s[ci]; t = xids[c * 64 + r]; }

            const int s = t_cur & 3;
            const float4* __restrict__ xrow = xs4 + t_cur * KR4;
            float acc0 = 0.f, acc1 = 0.f, acc2 = 0.f, acc3 = 0.f;
#pragma unroll
            for (int k4 = 0; k4 < KR4; ++k4) {
                const float4 xv = xrow[k4 ^ s];
                acc0 = fmaf(a[k4 * 4 + 0], xv.x, acc0);
                acc1 = fmaf(a[k4 * 4 + 1], xv.y, acc1);
                acc2 = fmaf(a[k4 * 4 + 2], xv.z, acc2);
                acc3 = fmaf(a[k4 * 4 + 3], xv.w, acc3);
            }
            scr[c_cur * 64 + r] = (acc0 + acc1) + (acc2 + acc3);
        }
    }
}

// ---- reduce: sum 256 k-partials per pair (4 rotating accumulators) ----
__global__ void reduce_kernel(float* __restrict__ out)
{
    const int p = blockIdx.x * blockDim.x + threadIdx.x;
    if (p >= NPAIR) return;
    float s0 = 0.f, s1 = 0.f, s2 = 0.f, s3 = 0.f;
#pragma unroll 8
    for (int kr = 0; kr < NKR; kr += 4) {
        s0 += g_scratch[(size_t)(kr + 0) * NPAIR + p];
        s1 += g_scratch[(size_t)(kr + 1) * NPAIR + p];
        s2 += g_scratch[(size_t)(kr + 2) * NPAIR + p];
        s3 += g_scratch[(size_t)(kr + 3) * NPAIR + p];
    }
    out[p] = (s0 + s1) + (s2 + s3);
}

extern "C" void kernel_launch(void* const* d_in, const int* in_sizes, int n_in,
                              void* d_out, int out_size)
{
    const float* x    = (const float*)d_in[0];
    const int*   xids = (const int*)  d_in[1];
    const int*   wids = (const int*)  d_in[2];
    const float* A    = (const float*)d_in[3];
    float*       out  = (float*)d_out;

    cudaFuncSetAttribute(lora_main,
                         cudaFuncAttributeMaxDynamicSharedMemorySize, SMEM_BYTES);

    lora_main<<<dim3(NKR, ASPLIT), NTHR, SMEM_BYTES>>>(x, xids, wids, A);
    reduce_kernel<<<(NPAIR + 255) / 256, 256>>>(out);
}

// round 8
// speedup vs baseline: 1.4415x; 1.4415x over previous
#include <cuda_runtime.h>
#include <cuda_fp16.h>

// CombinedLoraA: out[c, r] = sum_k x[xids[c*64+r], k] * A[wids[c], k, r]
//   x:[512,1,4096] f32  xids:[20480] i32  wids:[320] i32  A:[80,4096,64] f32
//   out:[320,1,64] f32
//
// R7: KR=32 (R3's sweet spot) + x staged in smem as FP16 (32 KB tile):
//  - 4 CTAs/SM (occ ~50% vs 31%), LDS bytes halved, conflicts over 4 groups.
//  - fp32 A, fp32 accumulate -> rel_err ~1e-4 (fp16 x rounding), 7x margin.
//  - in-CTA adapter grouping (no setup kernel); coalesced scratch + 8-acc
//    reduce kernel.

constexpr int KDIM   = 4096;
constexpr int RANK   = 64;
constexpr int CDIM   = 320;
constexpr int NADAPT = 80;
constexpr int NTOK   = 512;
constexpr int KR     = 32;               // k per range
constexpr int NKR    = KDIM / KR;        // 128
constexpr int ASPLIT = 7;                // grid 128*7 = 896 CTAs
constexpr int NTHR   = 256;
constexpr int NPAIR  = CDIM * RANK;      // 20480
constexpr int KQ     = KR / 8;           // 4 uint4 (8 fp16) slots per row

constexpr int SMEM_BYTES = NTOK * KR * 2            // x fp16 tile (32 KB)
                         + CDIM * 4                 // perm
                         + CDIM * 4                 // wid
                         + (NADAPT + 1) * 4;        // seg   -> ~35.2 KB

__device__ float g_scratch[NKR * NPAIR];            // 10.5 MB k-partials

static __device__ __forceinline__ __half2 u2h(unsigned u) {
    return *reinterpret_cast<__half2*>(&u);
}

// ---- main: one CTA = (k-range, adapter-slot) ----
__global__ __launch_bounds__(NTHR, 4) void lora_main(
    const float* __restrict__ x,
    const int*   __restrict__ xids,
    const int*   __restrict__ wids,
    const float* __restrict__ A)
{
    extern __shared__ float smem[];
    uint4* xs     = reinterpret_cast<uint4*>(smem);             // 512 rows x 4 slots
    int*   perm_s = reinterpret_cast<int*>(smem + NTOK * KR / 2);
    int*   wid_s  = perm_s + CDIM;
    int*   seg_s  = wid_s + CDIM;

    const int tid   = threadIdx.x;
    const int kr0   = blockIdx.x * KR;
    const int aslot = blockIdx.y;

    for (int i = tid; i < CDIM; i += NTHR) wid_s[i] = wids[i];

    // stage x k-range (f32 -> fp16), slot = k8 ^ (row & 3)
    for (int i = tid; i < NTOK * KQ; i += NTHR) {
        const int row = i >> 2, k8 = i & 3;
        const float* __restrict__ xp = x + (size_t)row * KDIM + kr0 + k8 * 8;
        const float4 v0 = *reinterpret_cast<const float4*>(xp);
        const float4 v1 = *reinterpret_cast<const float4*>(xp + 4);
        uint4 u;
        u.x = __half2_raw(__float22half2_rn(make_float2(v0.x, v0.y))).x |
              ((unsigned)__half2_raw(__float22half2_rn(make_float2(v0.x, v0.y))).y << 16);
        // build packed halves explicitly (avoid raw-bit fiddling ambiguity)
        __half2 h0 = __float22half2_rn(make_float2(v0.x, v0.y));
        __half2 h1 = __float22half2_rn(make_float2(v0.z, v0.w));
        __half2 h2 = __float22half2_rn(make_float2(v1.x, v1.y));
        __half2 h3 = __float22half2_rn(make_float2(v1.z, v1.w));
        u.x = *reinterpret_cast<unsigned*>(&h0);
        u.y = *reinterpret_cast<unsigned*>(&h1);
        u.z = *reinterpret_cast<unsigned*>(&h2);
        u.w = *reinterpret_cast<unsigned*>(&h3);
        xs[row * KQ + (k8 ^ (row & 3))] = u;
    }
    __syncthreads();

    // in-CTA adapter grouping: rank of (wid, c) -> perm; prefix counts -> seg
    for (int c = tid; c < CDIM; c += NTHR) {
        const int w = wid_s[c];
        int pos = 0;
#pragma unroll 8
        for (int c2 = 0; c2 < CDIM; ++c2) {
            const int w2 = wid_s[c2];
            pos += (w2 < w) || (w2 == w && c2 < c);
        }
        perm_s[pos] = c;
    }
    if (tid < NADAPT + 1) {
        int s = 0;
#pragma unroll 8
        for (int c2 = 0; c2 < CDIM; ++c2) s += (wid_s[c2] < tid);
        seg_s[tid] = s;
    }
    __syncthreads();

    const int r = tid & 63;          // rank index (lane-contiguous)
    const int g = tid >> 6;          // 4 independent thread-groups
    const int w_lo = (aslot * NADAPT) / ASPLIT;
    const int w_hi = ((aslot + 1) * NADAPT) / ASPLIT;

    float* __restrict__ scr = g_scratch + (size_t)blockIdx.x * NPAIR;

    for (int w = w_lo + g; w < w_hi; w += 4) {
        const int lo = seg_s[w], hi = seg_s[w + 1];
        if (lo >= hi) continue;

        // A[w, kr0..kr0+32, r] -> 32 registers (coalesced over r)
        float a[KR];
        const float* __restrict__ Ap = A + ((size_t)w * KDIM + kr0) * RANK + r;
#pragma unroll
        for (int j = 0; j < KR; ++j) a[j] = Ap[j * RANK];

        // software-pipelined token fetch
        int ci = lo;
        int c  = perm_s[ci];
        int t  = xids[c * 64 + r];
        while (ci < hi) {
            const int c_cur = c, t_cur = t;
            ++ci;
            if (ci < hi) { c = perm_s[ci]; t = xids[c * 64 + r]; }

            const int s = t_cur & 3;
            const uint4* __restrict__ xrow = xs + t_cur * KQ;
            float acc0 = 0.f, acc1 = 0.f, acc2 = 0.f, acc3 = 0.f;
#pragma unroll
            for (int k8 = 0; k8 < KQ; ++k8) {
                const uint4 hv = xrow[k8 ^ s];
                const float* __restrict__ ak = a + k8 * 8;
                const float2 f0 = __half22float2(u2h(hv.x));
                const float2 f1 = __half22float2(u2h(hv.y));
                const float2 f2 = __half22float2(u2h(hv.z));
                const float2 f3 = __half22float2(u2h(hv.w));
                acc0 = fmaf(ak[0], f0.x, acc0); acc1 = fmaf(ak[1], f0.y, acc1);
                acc2 = fmaf(ak[2], f1.x, acc2); acc3 = fmaf(ak[3], f1.y, acc3);
                acc0 = fmaf(ak[4], f2.x, acc0); acc1 = fmaf(ak[5], f2.y, acc1);
                acc2 = fmaf(ak[6], f3.x, acc2); acc3 = fmaf(ak[7], f3.y, acc3);
            }
            scr[c_cur * 64 + r] = (acc0 + acc1) + (acc2 + acc3);
        }
    }
}

// ---- reduce: sum 128 k-partials per pair (8 rotating accumulators) ----
__global__ void reduce_kernel(float* __restrict__ out)
{
    const int p = blockIdx.x * blockDim.x + threadIdx.x;
    if (p >= NPAIR) return;
    float s0=0.f,s1=0.f,s2=0.f,s3=0.f,s4=0.f,s5=0.f,s6=0.f,s7=0.f;
#pragma unroll 4
    for (int kr = 0; kr < NKR; kr += 8) {
        s0 += g_scratch[(size_t)(kr + 0) * NPAIR + p];
        s1 += g_scratch[(size_t)(kr + 1) * NPAIR + p];
        s2 += g_scratch[(size_t)(kr + 2) * NPAIR + p];
        s3 += g_scratch[(size_t)(kr + 3) * NPAIR + p];
        s4 += g_scratch[(size_t)(kr + 4) * NPAIR + p];
        s5 += g_scratch[(size_t)(kr + 5) * NPAIR + p];
        s6 += g_scratch[(size_t)(kr + 6) * NPAIR + p];
        s7 += g_scratch[(size_t)(kr + 7) * NPAIR + p];
    }
    out[p] = ((s0 + s1) + (s2 + s3)) + ((s4 + s5) + (s6 + s7));
}

extern "C" void kernel_launch(void* const* d_in, const int* in_sizes, int n_in,
                              void* d_out, int out_size)
{
    const float* x    = (const float*)d_in[0];
    const int*   xids = (const int*)  d_in[1];
    const int*   wids = (const int*)  d_in[2];
    const float* A    = (const float*)d_in[3];
    float*       out  = (float*)d_out;

    cudaFuncSetAttribute(lora_main,
                         cudaFuncAttributeMaxDynamicSharedMemorySize, SMEM_BYTES);

    lora_main<<<dim3(NKR, ASPLIT), NTHR, SMEM_BYTES>>>(x, xids, wids, A);
    reduce_kernel<<<(NPAIR + 127) / 128, 128>>>(out);
}

// round 9
// speedup vs baseline: 1.5040x; 1.0433x over previous
#include <cuda_runtime.h>

// CombinedLoraA: out[c, r] = sum_k x[xids[c*64+r], k] * A[wids[c], k, r]
//   x:[512,1,4096] f32  xids:[20480] i32  wids:[320] i32  A:[80,4096,64] f32
//   out:[320,1,64] f32
//
// R8: R3 data layout (KR=32 fp32 x-slice in smem, 8 XOR slot-groups,
// A[w,kr,r] in 32 regs) with 512-thread CTAs -> 2 CTAs/SM = 50% occ,
// in-CTA adapter grouping (no setup kernel), coalesced scratch STG,
// MLP-16 reduce kernel.

constexpr int KDIM   = 4096;
constexpr int RANK   = 64;
constexpr int CDIM   = 320;
constexpr int NADAPT = 80;
constexpr int NTOK   = 512;
constexpr int KR     = 32;               // k per range
constexpr int NKR    = KDIM / KR;        // 128
constexpr int ASPLIT = 4;                // grid 128*4 = 512 CTAs (2 waves @2/SM)
constexpr int NTHR   = 512;
constexpr int NGRP   = NTHR / 64;        // 8 thread-groups
constexpr int NPAIR  = CDIM * RANK;      // 20480

constexpr int SMEM_BYTES = NTOK * KR * 4            // x slice (64 KB)
                         + CDIM * 4                 // perm
                         + CDIM * 4                 // wid
                         + (NADAPT + 1) * 4;        // seg  -> ~66.8 KB

__device__ float g_scratch[NKR * NPAIR];            // 10.5 MB k-partials

// ---- main: one CTA = (k-range, adapter-slot) ----
__global__ __launch_bounds__(NTHR, 2) void lora_main(
    const float* __restrict__ x,
    const int*   __restrict__ xids,
    const int*   __restrict__ wids,
    const float* __restrict__ A)
{
    extern __shared__ float smem[];
    float4* xs4    = reinterpret_cast<float4*>(smem);           // 512 rows x 8 f4 slots
    int*    perm_s = reinterpret_cast<int*>(smem + NTOK * KR);
    int*    wid_s  = perm_s + CDIM;
    int*    seg_s  = wid_s + CDIM;

    const int tid   = threadIdx.x;
    const int kr0   = blockIdx.x * KR;
    const int aslot = blockIdx.y;

    for (int i = tid; i < CDIM; i += NTHR) wid_s[i] = wids[i];

    // stage x k-range for ALL 512 rows; slot = k4 ^ (row & 7)
    for (int i = tid; i < NTOK * 8; i += NTHR) {
        const int row = i >> 3, k4 = i & 7;
        const float4 v = *reinterpret_cast<const float4*>(
            x + (size_t)row * KDIM + kr0 + k4 * 4);
        xs4[row * 8 + (k4 ^ (row & 7))] = v;
    }
    __syncthreads();

    // in-CTA adapter grouping: rank of (wid, c) -> perm; prefix counts -> seg
    for (int c = tid; c < CDIM; c += NTHR) {
        const int w = wid_s[c];
        int pos = 0;
#pragma unroll 8
        for (int c2 = 0; c2 < CDIM; ++c2) {
            const int w2 = wid_s[c2];
            pos += (w2 < w) || (w2 == w && c2 < c);
        }
        perm_s[pos] = c;
    }
    if (tid < NADAPT + 1) {
        int s = 0;
#pragma unroll 8
        for (int c2 = 0; c2 < CDIM; ++c2) s += (wid_s[c2] < tid);
        seg_s[tid] = s;
    }
    __syncthreads();

    const int r = tid & 63;          // rank index (lane-contiguous)
    const int g = tid >> 6;          // 8 independent thread-groups
    const int w_lo = (aslot * NADAPT) / ASPLIT;
    const int w_hi = ((aslot + 1) * NADAPT) / ASPLIT;

    float* __restrict__ scr = g_scratch + (size_t)blockIdx.x * NPAIR;

    for (int w = w_lo + g; w < w_hi; w += NGRP) {
        const int lo = seg_s[w], hi = seg_s[w + 1];
        if (lo >= hi) continue;

        // A[w, kr0..kr0+32, r] -> 32 registers (coalesced over r)
        float a[KR];
        const float* __restrict__ Ap = A + ((size_t)w * KDIM + kr0) * RANK + r;
#pragma unroll
        for (int j = 0; j < KR; ++j) a[j] = Ap[j * RANK];

        // software-pipelined token fetch
        int ci = lo;
        int c  = perm_s[ci];
        int t  = xids[c * 64 + r];
        while (ci < hi) {
            const int c_cur = c, t_cur = t;
            ++ci;
            if (ci < hi) { c = perm_s[ci]; t = xids[c * 64 + r]; }

            const int s = t_cur & 7;
            const float4* __restrict__ xrow = xs4 + t_cur * 8;
            float acc0 = 0.f, acc1 = 0.f, acc2 = 0.f, acc3 = 0.f;
#pragma unroll
            for (int k4 = 0; k4 < 8; ++k4) {
                const float4 xv = xrow[k4 ^ s];
                acc0 = fmaf(a[k4 * 4 + 0], xv.x, acc0);
                acc1 = fmaf(a[k4 * 4 + 1], xv.y, acc1);
                acc2 = fmaf(a[k4 * 4 + 2], xv.z, acc2);
                acc3 = fmaf(a[k4 * 4 + 3], xv.w, acc3);
            }
            scr[c_cur * 64 + r] = (acc0 + acc1) + (acc2 + acc3);
        }
    }
}

// ---- reduce: 128 k-partials per pair, 16 rotating accumulators (MLP 16) ----
__global__ void reduce_kernel(float* __restrict__ out)
{
    const int p = blockIdx.x * blockDim.x + threadIdx.x;
    if (p >= NPAIR) return;
    float s[16];
#pragma unroll
    for (int i = 0; i < 16; ++i) s[i] = 0.f;
#pragma unroll
    for (int kr = 0; kr < NKR; kr += 16) {
#pragma unroll
        for (int i = 0; i < 16; ++i)
            s[i] += g_scratch[(size_t)(kr + i) * NPAIR + p];
    }
    float t0 = ((s[0]+s[1])+(s[2]+s[3])) + ((s[4]+s[5])+(s[6]+s[7]));
    float t1 = ((s[8]+s[9])+(s[10]+s[11])) + ((s[12]+s[13])+(s[14]+s[15]));
    out[p] = t0 + t1;
}

extern "C" void kernel_launch(void* const* d_in, const int* in_sizes, int n_in,
                              void* d_out, int out_size)
{
    const float* x    = (const float*)d_in[0];
    const int*   xids = (const int*)  d_in[1];
    const int*   wids = (const int*)  d_in[2];
    const float* A    = (const float*)d_in[3];
    float*       out  = (float*)d_out;

    cudaFuncSetAttribute(lora_main,
                         cudaFuncAttributeMaxDynamicSharedMemorySize, SMEM_BYTES);

    lora_main<<<dim3(NKR, ASPLIT), NTHR, SMEM_BYTES>>>(x, xids, wids, A);
    reduce_kernel<<<(NPAIR + 127) / 128, 128>>>(out);
}